// round 14
// baseline (speedup 1.0000x reference)
#include <cuda_runtime.h>
#include <cuda_bf16.h>
#include <math.h>

#define NE 2048
#define NP 32768
#define NBLK 512

// ---------------- global scratch (cross-block only) ----------------
__device__ float g_U[NE * 64];
__device__ float g_V[NE * 64];
__device__ float g_R[NP * 16];
__device__ float4 g_Z4[NE * 64];
__device__ float g_Xcol[NE * 64];
__device__ int g_count[4];
__device__ volatile int g_sense[4];

// ---------------- shared phase union ----------------
struct P0 { float efs[4][64]; float Ysh[4][4][64]; };
struct P1 { float W2s[64 * 32]; float W3s[32 * 16]; float b2s[32]; float b3s[16]; };
struct P2 { float Xcw[20][64]; float Xsh[4][4][64]; float hps[4][64]; float lv[4][16]; };
struct P3 { float4 Z4sh[20][64]; };
union SmemU { P0 p0; P1 p1; P2 p2; P3 p3; };

__device__ __forceinline__ void grid_barrier(int id) {
    __syncthreads();
    if (threadIdx.x == 0) {
        int s = g_sense[id];
        __threadfence();
        if (atomicAdd(&g_count[id], 1) == NBLK - 1) {
            g_count[id] = 0;
            __threadfence();
            g_sense[id] = 1 - s;
        } else {
            while (g_sense[id] == s) {}
        }
        __threadfence();
    }
    __syncthreads();
}

__global__ __launch_bounds__(256, 4)
void k_fused(const float* __restrict__ ef, const float* __restrict__ L1,
             const float* __restrict__ X,
             const float* __restrict__ W1, const float* __restrict__ b1,
             const float* __restrict__ W2, const float* __restrict__ b2,
             const float* __restrict__ W3, const float* __restrict__ b3,
             const float* __restrict__ Wh,
             const float* __restrict__ Ws1, const float* __restrict__ Ws2,
             const float* __restrict__ resW, const float* __restrict__ resb,
             const float* __restrict__ alpha, const float* __restrict__ beta,
             const int* __restrict__ eidx, const int* __restrict__ jiidx,
             float* __restrict__ out) {
    __shared__ SmemU su;
    __shared__ __align__(16) float4 offs4[4][64];
    __shared__ int jrel[4][16];
    __shared__ __align__(16) float sDb[4][16];
    __shared__ __align__(16) float sDinv[4][16];
    __shared__ float lvp[64];

    int tid = threadIdx.x;
    int i0 = blockIdx.x * 4;
    int nl = tid >> 6, f = tid & 63;
    int n = i0 + nl;

    // ================= phase 0: U, V, Xcol, Xt =================
    float4 xtr;
    {
        su.p0.efs[nl][f] = ef[n * 64 + f];
        float xr[4];
        #pragma unroll
        for (int b = 0; b < 4; b++) xr[b] = X[(4 * n + b) * 64 + f];
        g_Xcol[n * 64 + f] = 0.25f * (xr[0] + xr[1] + xr[2] + xr[3]);
        #pragma unroll
        for (int a = 0; a < 4; a++) {
            float y = 0.f;
            #pragma unroll
            for (int b = 0; b < 4; b++) y = fmaf(Ws1[a * 4 + b], xr[b], y);
            su.p0.Ysh[nl][a][f] = y;
        }
        __syncthreads();
        float u = b1[f], v = 0.f;
        #pragma unroll 8
        for (int k = 0; k < 64; k++) {
            float x = su.p0.efs[nl][k];
            u = fmaf(x, W1[k * 64 + f], u);
            v = fmaf(x, W1[(64 + k) * 64 + f], v);
        }
        g_U[n * 64 + f] = u;
        g_V[n * 64 + f] = v;
        float xt[4] = {0.f, 0.f, 0.f, 0.f};
        #pragma unroll 4
        for (int g = 0; g < 64; g++) {
            float w2 = Ws2[g * 64 + f];
            #pragma unroll
            for (int a = 0; a < 4; a++) xt[a] = fmaf(su.p0.Ysh[nl][a][g], w2, xt[a]);
        }
        xtr.x = xt[0]; xtr.y = xt[1]; xtr.z = xt[2]; xtr.w = xt[3];
    }
    grid_barrier(0);

    // ================= phase 1: pair MLP -> R, L1 gather =================
    {
        for (int i = tid; i < 64 * 32; i += 256) su.p1.W2s[i] = W2[i];
        for (int i = tid; i < 32 * 16; i += 256) su.p1.W3s[i] = W3[i];
        if (tid < 32) su.p1.b2s[tid] = b2[tid];
        if (tid < 16) su.p1.b3s[tid] = b3[tid];
        __syncthreads();
        int w = tid >> 5, lane = tid & 31;
        int p0p = (blockIdx.x * 8 + w) * 8;   // pairs w*8..w*8+7 of this block

        if (lane < 8) {
            int p = p0p + lane;
            int ii = eidx[2 * p], jj = eidx[2 * p + 1];
            lvp[w * 8 + lane] = L1[(size_t)ii * NE + jj];
        }

        float hx[8], hy[8];
        #pragma unroll
        for (int pi = 0; pi < 8; pi++) {
            int p = p0p + pi;
            int ii = eidx[2 * p], jj = eidx[2 * p + 1];
            float2 uu = *(const float2*)&g_U[ii * 64 + 2 * lane];
            float2 vv = *(const float2*)&g_V[jj * 64 + 2 * lane];
            hx[pi] = fmaxf(uu.x + vv.x, 0.f);
            hy[pi] = fmaxf(uu.y + vv.y, 0.f);
        }

        float c[8];
        float b2v = su.p1.b2s[lane];
        #pragma unroll
        for (int pi = 0; pi < 8; pi++) c[pi] = b2v;
        #pragma unroll
        for (int k = 0; k < 64; k++) {
            float wv = su.p1.W2s[k * 32 + lane];
            int src = k >> 1;
            #pragma unroll
            for (int pi = 0; pi < 8; pi++) {
                float hval = __shfl_sync(0xffffffffu, (k & 1) ? hy[pi] : hx[pi], src);
                c[pi] = fmaf(hval, wv, c[pi]);
            }
        }
        #pragma unroll
        for (int pi = 0; pi < 8; pi++) c[pi] = fmaxf(c[pi], 0.f);

        float r[8];
        float b3v = (lane < 16) ? su.p1.b3s[lane] : 0.f;
        #pragma unroll
        for (int pi = 0; pi < 8; pi++) r[pi] = b3v;
        #pragma unroll
        for (int k = 0; k < 32; k++) {
            float wv = (lane < 16) ? su.p1.W3s[k * 16 + lane] : 0.f;
            #pragma unroll
            for (int pi = 0; pi < 8; pi++) {
                float hval = __shfl_sync(0xffffffffu, c[pi], k);
                r[pi] = fmaf(hval, wv, r[pi]);
            }
        }
        if (lane < 16) {
            #pragma unroll
            for (int pi = 0; pi < 8; pi++)
                g_R[(p0p + pi) * 16 + lane] = r[pi];
        }
    }
    grid_barrier(1);

    // ================= phase 2: diag/Jacobi/off + Z + hodge + residual ===
    float pr[4];
    {
        int w = tid >> 5, lane = tid & 31;

        // A: diag (warp per node, warps 0-3)
        if (w < 4) {
            int node = i0 + w;
            float Fm[16];
            #pragma unroll
            for (int x = 0; x < 16; x++) Fm[x] = 0.f;
            if (lane < 16) {
                int p = node * 16 + lane;
                float4 r0 = *(const float4*)&g_R[p * 16];
                float4 r1 = *(const float4*)&g_R[p * 16 + 4];
                float4 r2 = *(const float4*)&g_R[p * 16 + 8];
                float4 r3 = *(const float4*)&g_R[p * 16 + 12];
                float Rv[16] = {r0.x, r0.y, r0.z, r0.w, r1.x, r1.y, r1.z, r1.w,
                                r2.x, r2.y, r2.z, r2.w, r3.x, r3.y, r3.z, r3.w};
                #pragma unroll
                for (int a = 0; a < 4; a++)
                    #pragma unroll
                    for (int b = 0; b < 4; b++) {
                        float s = 0.f;
                        #pragma unroll
                        for (int cc = 0; cc < 4; cc++) s = fmaf(Rv[cc * 4 + a], Rv[cc * 4 + b], s);
                        Fm[a * 4 + b] = s;
                    }
            }
            #pragma unroll
            for (int x = 0; x < 16; x++) {
                Fm[x] += __shfl_down_sync(0xffffffffu, Fm[x], 8);
                Fm[x] += __shfl_down_sync(0xffffffffu, Fm[x], 4);
                Fm[x] += __shfl_down_sync(0xffffffffu, Fm[x], 2);
                Fm[x] += __shfl_down_sync(0xffffffffu, Fm[x], 1);
            }
            if (lane == 0) {
                #pragma unroll
                for (int x = 0; x < 16; x++) sDb[w][x] = Fm[x];
            }
        }
        __syncthreads();

        // B: off blocks (tid<64) + Jacobi (tid 64..67)
        if (tid < 64) {
            int p = i0 * 16 + tid;
            int jp = jiidx[p];
            float l = lvp[tid];
            float msg = (l > 0.f) ? -1.f : ((l < 0.f) ? 1.f : 0.f);
            float4 a0 = *(const float4*)&g_R[jp * 16];
            float4 a1 = *(const float4*)&g_R[jp * 16 + 4];
            float4 a2 = *(const float4*)&g_R[jp * 16 + 8];
            float4 a3 = *(const float4*)&g_R[jp * 16 + 12];
            float4 b0 = *(const float4*)&g_R[p * 16];
            float4 b1v = *(const float4*)&g_R[p * 16 + 4];
            float4 b2v = *(const float4*)&g_R[p * 16 + 8];
            float4 b3v = *(const float4*)&g_R[p * 16 + 12];
            float Ra[16] = {a0.x, a0.y, a0.z, a0.w, a1.x, a1.y, a1.z, a1.w,
                            a2.x, a2.y, a2.z, a2.w, a3.x, a3.y, a3.z, a3.w};
            float Rb[16] = {b0.x, b0.y, b0.z, b0.w, b1v.x, b1v.y, b1v.z, b1v.w,
                            b2v.x, b2v.y, b2v.z, b2v.w, b3v.x, b3v.y, b3v.z, b3v.w};
            int nn = tid >> 4, kk = tid & 15;
            #pragma unroll
            for (int a = 0; a < 4; a++) {
                float4 row;
                float* rp = (float*)&row;
                #pragma unroll
                for (int b = 0; b < 4; b++) {
                    float m = 0.f;
                    #pragma unroll
                    for (int cc = 0; cc < 4; cc++) m = fmaf(Ra[cc * 4 + a], Rb[cc * 4 + b], m);
                    rp[b] = msg * m;
                }
                offs4[nn][kk * 4 + a] = row;
            }
        } else if (tid < 68) {
            int nn = tid - 64;
            const float eps = 1e-4f;
            float A[4][4], V[4][4];
            #pragma unroll
            for (int a = 0; a < 4; a++)
                #pragma unroll
                for (int b = 0; b < 4; b++) {
                    A[a][b] = 0.5f * (sDb[nn][a * 4 + b] + sDb[nn][b * 4 + a]);
                    V[a][b] = (a == b) ? 1.f : 0.f;
                }
            #pragma unroll
            for (int a = 0; a < 4; a++) A[a][a] += eps;
            const int PI[6] = {0, 0, 0, 1, 1, 2};
            const int QI[6] = {1, 2, 3, 2, 3, 3};
            #pragma unroll
            for (int sweep = 0; sweep < 6; sweep++) {
                #pragma unroll
                for (int rr = 0; rr < 6; rr++) {
                    int p = PI[rr], q = QI[rr];
                    float apq = A[p][q];
                    if (fabsf(apq) > 1e-20f) {
                        float theta = (A[q][q] - A[p][p]) / (2.f * apq);
                        float t = copysignf(1.f, theta) / (fabsf(theta) + sqrtf(theta * theta + 1.f));
                        float cth = rsqrtf(t * t + 1.f);
                        float sth = t * cth;
                        float app = A[p][p], aqq = A[q][q];
                        A[p][p] = app - t * apq;
                        A[q][q] = aqq + t * apq;
                        A[p][q] = 0.f; A[q][p] = 0.f;
                        #pragma unroll
                        for (int k = 0; k < 4; k++) {
                            if (k != p && k != q) {
                                float akp = A[k][p], akq = A[k][q];
                                A[k][p] = cth * akp - sth * akq; A[p][k] = A[k][p];
                                A[k][q] = sth * akp + cth * akq; A[q][k] = A[k][q];
                            }
                        }
                        #pragma unroll
                        for (int k = 0; k < 4; k++) {
                            float vkp = V[k][p], vkq = V[k][q];
                            V[k][p] = cth * vkp - sth * vkq;
                            V[k][q] = sth * vkp + cth * vkq;
                        }
                    }
                }
            }
            float invs[4];
            #pragma unroll
            for (int k = 0; k < 4; k++) invs[k] = rsqrtf(fmaxf(A[k][k], eps));
            #pragma unroll
            for (int a = 0; a < 4; a++)
                #pragma unroll
                for (int b = 0; b < 4; b++) {
                    float s = 0.f;
                    #pragma unroll
                    for (int k = 0; k < 4; k++) s = fmaf(V[a][k] * invs[k], V[b][k], s);
                    sDinv[nn][a * 4 + b] = s;
                }
        }

        // staging: Xcol window, X rows, jrel/lv
        #pragma unroll
        for (int t = 0; t < 5; t++) {
            int idx = tid + t * 256;
            int row = idx >> 6, ff = idx & 63;
            int src = (i0 - 8 + row) & (NE - 1);
            su.p2.Xcw[row][ff] = g_Xcol[src * 64 + ff];
        }
        #pragma unroll
        for (int t = 0; t < 4; t++) {
            int idx = tid + t * 256;
            int nn = idx >> 8, rest = idx & 255;
            int b = rest >> 6, ff = rest & 63;
            su.p2.Xsh[nn][b][ff] = X[(4 * (i0 + nn) + b) * 64 + ff];
        }
        if (tid < 64) {
            int nn = tid >> 4, k = tid & 15;
            int pp = (i0 + nn) * 16 + k;
            int j = eidx[2 * pp + 1];
            jrel[nn][k] = (j - i0 + 8) & (NE - 1);
            su.p2.lv[nn][k] = fabsf(lvp[tid]);
        }
        __syncthreads();

        // Z = Dinv @ Xt (xt carried in registers from phase 0)
        {
            float dv[16];
            #pragma unroll
            for (int x = 0; x < 16; x++) dv[x] = sDinv[nl][x];
            float4 z;
            z.x = fmaf(dv[0], xtr.x, fmaf(dv[1], xtr.y, fmaf(dv[2], xtr.z, dv[3] * xtr.w)));
            z.y = fmaf(dv[4], xtr.x, fmaf(dv[5], xtr.y, fmaf(dv[6], xtr.z, dv[7] * xtr.w)));
            z.z = fmaf(dv[8], xtr.x, fmaf(dv[9], xtr.y, fmaf(dv[10], xtr.z, dv[11] * xtr.w)));
            z.w = fmaf(dv[12], xtr.x, fmaf(dv[13], xtr.y, fmaf(dv[14], xtr.z, dv[15] * xtr.w)));
            g_Z4[n * 64 + f] = z;
        }

        // hodge + residual partial -> pr registers
        float s = 0.f;
        #pragma unroll
        for (int p = 0; p < 16; p++) s += su.p2.lv[nl][p];
        float inv = 1.f / (s + 1e-8f);
        float hp = su.p2.Xcw[8 + nl][f];
        #pragma unroll
        for (int p = 0; p < 16; p++)
            hp = fmaf(su.p2.lv[nl][p] * inv, su.p2.Xcw[jrel[nl][p]][f], hp);
        su.p2.hps[nl][f] = hp;
        __syncthreads();
        float h = 0.f;
        #pragma unroll 4
        for (int g = 0; g < 64; g++) h = fmaf(su.p2.hps[nl][g], Wh[g * 64 + f], h);
        float sa = 1.f / (1.f + expf(-alpha[0]));
        float bb = resb[f];
        #pragma unroll
        for (int b = 0; b < 4; b++) pr[b] = bb;
        #pragma unroll 4
        for (int k = 0; k < 64; k++) {
            float wv = resW[k * 64 + f];
            #pragma unroll
            for (int b = 0; b < 4; b++) pr[b] = fmaf(su.p2.Xsh[nl][b][k], wv, pr[b]);
        }
        #pragma unroll
        for (int b = 0; b < 4; b++) pr[b] -= sa * h;
    }
    grid_barrier(2);

    // ================= phase 3: sheaf + combine =================
    {
        #pragma unroll
        for (int t = 0; t < 5; t++) {
            int idx = tid + t * 256;
            int row = idx >> 6, ff = idx & 63;
            int src = (i0 - 8 + row) & (NE - 1);
            su.p3.Z4sh[row][ff] = g_Z4[src * 64 + ff];
        }
        __syncthreads();

        float4 zi = su.p3.Z4sh[8 + nl][f];
        float accs[4];
        #pragma unroll
        for (int a = 0; a < 4; a++) {
            float4 d = *(const float4*)&sDb[nl][4 * a];
            accs[a] = fmaf(d.x, zi.x, fmaf(d.y, zi.y, fmaf(d.z, zi.z, d.w * zi.w)));
        }
        #pragma unroll
        for (int k = 0; k < 16; k++) {
            float4 zj = su.p3.Z4sh[jrel[nl][k]][f];
            #pragma unroll
            for (int a = 0; a < 4; a++) {
                float4 o = offs4[nl][k * 4 + a];
                accs[a] = fmaf(o.x, zj.x, fmaf(o.y, zj.y, fmaf(o.z, zj.z, fmaf(o.w, zj.w, accs[a]))));
            }
        }
        float sh[4];
        #pragma unroll
        for (int a = 0; a < 4; a++) {
            float4 d = *(const float4*)&sDinv[nl][4 * a];
            sh[a] = fmaf(d.x, accs[0], fmaf(d.y, accs[1], fmaf(d.z, accs[2], d.w * accs[3])));
        }

        float sb = 1.f / (1.f + expf(-beta[0]));
        int i = i0 + nl;
        #pragma unroll
        for (int b = 0; b < 4; b++) {
            float e = (sh[b] > 0.f) ? sh[b] : expm1f(sh[b]);
            out[(4 * i + b) * 64 + f] = pr[b] - sb * e;
        }
    }
}

extern "C" void kernel_launch(void* const* d_in, const int* in_sizes, int n_in,
                              void* d_out, int out_size) {
    const float* ef    = (const float*)d_in[0];
    const float* L1    = (const float*)d_in[1];
    const float* X     = (const float*)d_in[2];
    const float* W1    = (const float*)d_in[3];
    const float* b1    = (const float*)d_in[4];
    const float* W2    = (const float*)d_in[5];
    const float* b2    = (const float*)d_in[6];
    const float* W3    = (const float*)d_in[7];
    const float* b3    = (const float*)d_in[8];
    const float* Wh    = (const float*)d_in[9];
    const float* Ws1   = (const float*)d_in[10];
    const float* Ws2   = (const float*)d_in[11];
    const float* resW  = (const float*)d_in[12];
    const float* resb  = (const float*)d_in[13];
    const float* alpha = (const float*)d_in[14];
    const float* beta  = (const float*)d_in[15];
    const int*   eidx  = (const int*)d_in[16];
    const int*   jiidx = (const int*)d_in[17];
    float* out = (float*)d_out;

    k_fused<<<NBLK, 256>>>(ef, L1, X, W1, b1, W2, b2, W3, b3, Wh,
                           Ws1, Ws2, resW, resb, alpha, beta, eidx, jiidx, out);
}

// round 15
// speedup vs baseline: 1.0370x; 1.0370x over previous
#include <cuda_runtime.h>
#include <cuda_bf16.h>
#include <math.h>

#define NE 2048
#define NP 32768

// ---------------- static device scratch ----------------
__device__ float g_U[NE * 64];
__device__ float g_V[NE * 64];
__device__ float g_R[NP * 16];
__device__ float4 g_off4[NP * 4];
__device__ float g_lvals[NP];
__device__ float g_diag[NE * 16];
__device__ float g_Dinv[NE * 16];
__device__ float4 g_Z4[NE * 64];
__device__ float4 g_Xt4[NE * 64];
__device__ float4 g_P4[NE * 64];
__device__ float g_Xcol[NE * 64];

// ---------------- K0: U, V, Xcol, Xt (R11 winner) -----------------------
__global__ void k_pre(const float* __restrict__ ef, const float* __restrict__ W1,
                      const float* __restrict__ b1, const float* __restrict__ X,
                      const float* __restrict__ Ws1, const float* __restrict__ Ws2) {
    int nl = threadIdx.x >> 6, f = threadIdx.x & 63;
    int n = blockIdx.x * 4 + nl;
    __shared__ float efs[4][64];
    __shared__ float Ysh[4][4][64];
    efs[nl][f] = ef[n * 64 + f];
    float xr[4];
    #pragma unroll
    for (int b = 0; b < 4; b++) xr[b] = X[(4 * n + b) * 64 + f];
    g_Xcol[n * 64 + f] = 0.25f * (xr[0] + xr[1] + xr[2] + xr[3]);
    #pragma unroll
    for (int a = 0; a < 4; a++) {
        float y = 0.f;
        #pragma unroll
        for (int b = 0; b < 4; b++) y = fmaf(Ws1[a * 4 + b], xr[b], y);
        Ysh[nl][a][f] = y;
    }
    __syncthreads();
    float u = b1[f], v = 0.f;
    #pragma unroll 8
    for (int k = 0; k < 64; k++) {
        float x = efs[nl][k];
        u = fmaf(x, W1[k * 64 + f], u);
        v = fmaf(x, W1[(64 + k) * 64 + f], v);
    }
    g_U[n * 64 + f] = u;
    g_V[n * 64 + f] = v;
    float xt[4] = {0.f, 0.f, 0.f, 0.f};
    #pragma unroll 4
    for (int g = 0; g < 64; g++) {
        float w2 = Ws2[g * 64 + f];
        #pragma unroll
        for (int a = 0; a < 4; a++) xt[a] = fmaf(Ysh[nl][a][g], w2, xt[a]);
    }
    float4 o;
    o.x = xt[0]; o.y = xt[1]; o.z = xt[2]; o.w = xt[3];
    g_Xt4[n * 64 + f] = o;
}

// ---------------- K1: MLP tail -> R (grid 1024, 4 pairs/warp) -----------
__global__ void k_pair(const float* __restrict__ L1,
                       const float* __restrict__ W2, const float* __restrict__ b2,
                       const float* __restrict__ W3, const float* __restrict__ b3,
                       const int* __restrict__ eidx) {
    __shared__ float W2s[64 * 32];
    __shared__ float W3s[32 * 16];
    __shared__ float b2s[32], b3s[16];
    int tid = threadIdx.x;
    for (int i = tid; i < 64 * 32; i += 256) W2s[i] = W2[i];
    for (int i = tid; i < 32 * 16; i += 256) W3s[i] = W3[i];
    if (tid < 32) b2s[tid] = b2[tid];
    if (tid < 16) b3s[tid] = b3[tid];
    __syncthreads();
    int w = tid >> 5, lane = tid & 31;
    int gw = blockIdx.x * 8 + w;          // 8192 warps
    int p0 = gw * 4;

    if (lane < 4) {
        int p = p0 + lane;
        int ii = eidx[2 * p], jj = eidx[2 * p + 1];
        g_lvals[p] = L1[(size_t)ii * NE + jj];
    }

    float hx[4], hy[4];
    #pragma unroll
    for (int pi = 0; pi < 4; pi++) {
        int p = p0 + pi;
        int ii = eidx[2 * p], jj = eidx[2 * p + 1];
        float2 uu = *(const float2*)&g_U[ii * 64 + 2 * lane];
        float2 vv = *(const float2*)&g_V[jj * 64 + 2 * lane];
        hx[pi] = fmaxf(uu.x + vv.x, 0.f);
        hy[pi] = fmaxf(uu.y + vv.y, 0.f);
    }

    float c[4];
    float b2v = b2s[lane];
    #pragma unroll
    for (int pi = 0; pi < 4; pi++) c[pi] = b2v;
    #pragma unroll
    for (int k = 0; k < 64; k++) {
        float wv = W2s[k * 32 + lane];
        int src = k >> 1;
        #pragma unroll
        for (int pi = 0; pi < 4; pi++) {
            float hval = __shfl_sync(0xffffffffu, (k & 1) ? hy[pi] : hx[pi], src);
            c[pi] = fmaf(hval, wv, c[pi]);
        }
    }
    #pragma unroll
    for (int pi = 0; pi < 4; pi++) c[pi] = fmaxf(c[pi], 0.f);

    float r[4];
    float b3v = (lane < 16) ? b3s[lane] : 0.f;
    #pragma unroll
    for (int pi = 0; pi < 4; pi++) r[pi] = b3v;
    #pragma unroll
    for (int k = 0; k < 32; k++) {
        float wv = (lane < 16) ? W3s[k * 16 + lane] : 0.f;
        #pragma unroll
        for (int pi = 0; pi < 4; pi++) {
            float hval = __shfl_sync(0xffffffffu, c[pi], k);
            r[pi] = fmaf(hval, wv, r[pi]);
        }
    }
    if (lane < 16) {
        #pragma unroll
        for (int pi = 0; pi < 4; pi++)
            g_R[(p0 + pi) * 16 + lane] = r[pi];
    }
}

// ---------------- K2: diag/Jacobi/off + Z + hodge + residual (R11) ------
__global__ void k_mid(const int* __restrict__ eidx, const int* __restrict__ jiidx,
                      const float* __restrict__ Wh, const float* __restrict__ X,
                      const float* __restrict__ resW, const float* __restrict__ resb,
                      const float* __restrict__ alpha) {
    __shared__ float sDb[4][16];
    __shared__ float sDinv[4][16];
    __shared__ float Xcw[20][64];
    __shared__ float Xsh[4][4][64];
    __shared__ float hps[4][64];
    __shared__ int jrel[4][16];
    __shared__ float lv[4][16];
    int tid = threadIdx.x;
    int w = tid >> 5, lane = tid & 31;
    int i0 = blockIdx.x * 4;

    if (w < 4) {
        int node = i0 + w;
        float Fm[16];
        #pragma unroll
        for (int x = 0; x < 16; x++) Fm[x] = 0.f;
        if (lane < 16) {
            int p = node * 16 + lane;
            float4 r0 = *(const float4*)&g_R[p * 16];
            float4 r1 = *(const float4*)&g_R[p * 16 + 4];
            float4 r2 = *(const float4*)&g_R[p * 16 + 8];
            float4 r3 = *(const float4*)&g_R[p * 16 + 12];
            float Rv[16] = {r0.x, r0.y, r0.z, r0.w, r1.x, r1.y, r1.z, r1.w,
                            r2.x, r2.y, r2.z, r2.w, r3.x, r3.y, r3.z, r3.w};
            #pragma unroll
            for (int a = 0; a < 4; a++)
                #pragma unroll
                for (int b = 0; b < 4; b++) {
                    float s = 0.f;
                    #pragma unroll
                    for (int c = 0; c < 4; c++) s = fmaf(Rv[c * 4 + a], Rv[c * 4 + b], s);
                    Fm[a * 4 + b] = s;
                }
        }
        #pragma unroll
        for (int x = 0; x < 16; x++) {
            Fm[x] += __shfl_down_sync(0xffffffffu, Fm[x], 8);
            Fm[x] += __shfl_down_sync(0xffffffffu, Fm[x], 4);
            Fm[x] += __shfl_down_sync(0xffffffffu, Fm[x], 2);
            Fm[x] += __shfl_down_sync(0xffffffffu, Fm[x], 1);
        }
        if (lane == 0) {
            #pragma unroll
            for (int x = 0; x < 16; x++) { sDb[w][x] = Fm[x]; g_diag[node * 16 + x] = Fm[x]; }
        }
    }
    __syncthreads();

    if (tid < 64) {
        int p = i0 * 16 + tid;
        int jp = jiidx[p];
        float l = g_lvals[p];
        float msg = (l > 0.f) ? -1.f : ((l < 0.f) ? 1.f : 0.f);
        float4 a0 = *(const float4*)&g_R[jp * 16];
        float4 a1 = *(const float4*)&g_R[jp * 16 + 4];
        float4 a2 = *(const float4*)&g_R[jp * 16 + 8];
        float4 a3 = *(const float4*)&g_R[jp * 16 + 12];
        float4 b0 = *(const float4*)&g_R[p * 16];
        float4 b1v = *(const float4*)&g_R[p * 16 + 4];
        float4 b2v = *(const float4*)&g_R[p * 16 + 8];
        float4 b3v = *(const float4*)&g_R[p * 16 + 12];
        float Ra[16] = {a0.x, a0.y, a0.z, a0.w, a1.x, a1.y, a1.z, a1.w,
                        a2.x, a2.y, a2.z, a2.w, a3.x, a3.y, a3.z, a3.w};
        float Rb[16] = {b0.x, b0.y, b0.z, b0.w, b1v.x, b1v.y, b1v.z, b1v.w,
                        b2v.x, b2v.y, b2v.z, b2v.w, b3v.x, b3v.y, b3v.z, b3v.w};
        #pragma unroll
        for (int a = 0; a < 4; a++) {
            float4 row;
            float* rp = (float*)&row;
            #pragma unroll
            for (int b = 0; b < 4; b++) {
                float m = 0.f;
                #pragma unroll
                for (int c = 0; c < 4; c++) m = fmaf(Ra[c * 4 + a], Rb[c * 4 + b], m);
                rp[b] = msg * m;
            }
            g_off4[p * 4 + a] = row;
        }
    } else if (tid < 68) {
        int nl = tid - 64;
        const float eps = 1e-4f;
        float A[4][4], V[4][4];
        #pragma unroll
        for (int a = 0; a < 4; a++)
            #pragma unroll
            for (int b = 0; b < 4; b++) {
                A[a][b] = 0.5f * (sDb[nl][a * 4 + b] + sDb[nl][b * 4 + a]);
                V[a][b] = (a == b) ? 1.f : 0.f;
            }
        #pragma unroll
        for (int a = 0; a < 4; a++) A[a][a] += eps;
        const int PI[6] = {0, 0, 0, 1, 1, 2};
        const int QI[6] = {1, 2, 3, 2, 3, 3};
        #pragma unroll
        for (int sweep = 0; sweep < 6; sweep++) {
            #pragma unroll
            for (int r = 0; r < 6; r++) {
                int p = PI[r], q = QI[r];
                float apq = A[p][q];
                if (fabsf(apq) > 1e-20f) {
                    float theta = (A[q][q] - A[p][p]) / (2.f * apq);
                    float t = copysignf(1.f, theta) / (fabsf(theta) + sqrtf(theta * theta + 1.f));
                    float cth = rsqrtf(t * t + 1.f);
                    float sth = t * cth;
                    float app = A[p][p], aqq = A[q][q];
                    A[p][p] = app - t * apq;
                    A[q][q] = aqq + t * apq;
                    A[p][q] = 0.f; A[q][p] = 0.f;
                    #pragma unroll
                    for (int k = 0; k < 4; k++) {
                        if (k != p && k != q) {
                            float akp = A[k][p], akq = A[k][q];
                            A[k][p] = cth * akp - sth * akq; A[p][k] = A[k][p];
                            A[k][q] = sth * akp + cth * akq; A[q][k] = A[k][q];
                        }
                    }
                    #pragma unroll
                    for (int k = 0; k < 4; k++) {
                        float vkp = V[k][p], vkq = V[k][q];
                        V[k][p] = cth * vkp - sth * vkq;
                        V[k][q] = sth * vkp + cth * vkq;
                    }
                }
            }
        }
        float invs[4];
        #pragma unroll
        for (int k = 0; k < 4; k++) invs[k] = rsqrtf(fmaxf(A[k][k], eps));
        int gnode = i0 + nl;
        #pragma unroll
        for (int a = 0; a < 4; a++)
            #pragma unroll
            for (int b = 0; b < 4; b++) {
                float s = 0.f;
                #pragma unroll
                for (int k = 0; k < 4; k++) s = fmaf(V[a][k] * invs[k], V[b][k], s);
                sDinv[nl][a * 4 + b] = s;
                g_Dinv[gnode * 16 + a * 4 + b] = s;
            }
    }

    #pragma unroll
    for (int t = 0; t < 5; t++) {
        int idx = tid + t * 256;
        int row = idx >> 6, ff = idx & 63;
        int src = (i0 - 8 + row) & (NE - 1);
        Xcw[row][ff] = g_Xcol[src * 64 + ff];
    }
    #pragma unroll
    for (int t = 0; t < 4; t++) {
        int idx = tid + t * 256;
        int nn = idx >> 8, rest = idx & 255;
        int b = rest >> 6, ff = rest & 63;
        Xsh[nn][b][ff] = X[(4 * (i0 + nn) + b) * 64 + ff];
    }
    if (tid < 64) {
        int nn = tid >> 4, k = tid & 15;
        int pp = (i0 + nn) * 16 + k;
        int j = eidx[2 * pp + 1];
        jrel[nn][k] = (j - i0 + 8) & (NE - 1);
        lv[nn][k] = fabsf(g_lvals[pp]);
    }
    __syncthreads();

    int nl = tid >> 6, f = tid & 63;
    int n = i0 + nl;

    {
        float4 xt = g_Xt4[n * 64 + f];
        float dv[16];
        #pragma unroll
        for (int x = 0; x < 16; x++) dv[x] = sDinv[nl][x];
        float4 z;
        z.x = fmaf(dv[0], xt.x, fmaf(dv[1], xt.y, fmaf(dv[2], xt.z, dv[3] * xt.w)));
        z.y = fmaf(dv[4], xt.x, fmaf(dv[5], xt.y, fmaf(dv[6], xt.z, dv[7] * xt.w)));
        z.z = fmaf(dv[8], xt.x, fmaf(dv[9], xt.y, fmaf(dv[10], xt.z, dv[11] * xt.w)));
        z.w = fmaf(dv[12], xt.x, fmaf(dv[13], xt.y, fmaf(dv[14], xt.z, dv[15] * xt.w)));
        g_Z4[n * 64 + f] = z;
    }

    float s = 0.f;
    #pragma unroll
    for (int p = 0; p < 16; p++) s += lv[nl][p];
    float inv = 1.f / (s + 1e-8f);
    float hp = Xcw[8 + nl][f];
    #pragma unroll
    for (int p = 0; p < 16; p++)
        hp = fmaf(lv[nl][p] * inv, Xcw[jrel[nl][p]][f], hp);
    hps[nl][f] = hp;
    __syncthreads();
    float h = 0.f;
    #pragma unroll 4
    for (int g = 0; g < 64; g++) h = fmaf(hps[nl][g], Wh[g * 64 + f], h);
    float sa = 1.f / (1.f + expf(-alpha[0]));
    float bb = resb[f];
    float r[4];
    #pragma unroll
    for (int b = 0; b < 4; b++) r[b] = bb;
    #pragma unroll 4
    for (int k = 0; k < 64; k++) {
        float wv = resW[k * 64 + f];
        #pragma unroll
        for (int b = 0; b < 4; b++) r[b] = fmaf(Xsh[nl][b][k], wv, r[b]);
    }
    float4 pr;
    pr.x = r[0] - sa * h; pr.y = r[1] - sa * h;
    pr.z = r[2] - sa * h; pr.w = r[3] - sa * h;
    g_P4[n * 64 + f] = pr;
}

// ---------------- K3: sheaf + combine, 512-thread blocks ----------------
// grid 512, block 512, 4 nodes/block. h = tid>>8 splits the 16-neighbor
// loop (8 each); partials combine via shared. Window staged once.
__global__ __launch_bounds__(512)
void k_out(const int* __restrict__ eidx, const float* __restrict__ beta,
           float* __restrict__ out) {
    int tid = threadIdx.x;
    int h = tid >> 8;                 // 0..1
    int nl = (tid >> 6) & 3, f = tid & 63;
    int i0 = blockIdx.x * 4;
    int i = i0 + nl;
    __shared__ float4 Z4sh[20][64];
    __shared__ float4 offs4[4][64];
    __shared__ float accsp[2][4][4][64];
    __shared__ int jrel[4][16];

    #pragma unroll
    for (int t = 0; t < 3; t++) {
        int idx = tid + t * 512;
        if (idx < 1280) {
            int row = idx >> 6, ff = idx & 63;
            int src = (i0 - 8 + row) & (NE - 1);
            Z4sh[row][ff] = g_Z4[src * 64 + ff];
        }
    }
    if (h == 0) offs4[nl][f] = g_off4[i * 64 + f];
    if (tid < 64) {
        int nn = tid >> 4, kk = tid & 15;
        int pp = (i0 + nn) * 16 + kk;
        int j = eidx[2 * pp + 1];
        jrel[nn][kk] = (j - i0 + 8) & (NE - 1);
    }
    __syncthreads();

    // partial sheaf: h covers neighbors 8h..8h+7; h=0 adds diag term
    float accs[4] = {0.f, 0.f, 0.f, 0.f};
    if (h == 0) {
        float4 zi = Z4sh[8 + nl][f];
        const float4* dgr = (const float4*)&g_diag[i * 16];
        #pragma unroll
        for (int a = 0; a < 4; a++) {
            float4 d = dgr[a];
            accs[a] = fmaf(d.x, zi.x, fmaf(d.y, zi.y, fmaf(d.z, zi.z, d.w * zi.w)));
        }
    }
    #pragma unroll
    for (int kk = 0; kk < 8; kk++) {
        int k = 8 * h + kk;
        float4 zj = Z4sh[jrel[nl][k]][f];
        #pragma unroll
        for (int a = 0; a < 4; a++) {
            float4 o = offs4[nl][k * 4 + a];
            accs[a] = fmaf(o.x, zj.x, fmaf(o.y, zj.y, fmaf(o.z, zj.z, fmaf(o.w, zj.w, accs[a]))));
        }
    }
    #pragma unroll
    for (int a = 0; a < 4; a++) accsp[h][nl][a][f] = accs[a];
    __syncthreads();

    // combine: thread (h,nl,f) produces output rows 2h, 2h+1
    float ac[4];
    #pragma unroll
    for (int a = 0; a < 4; a++) ac[a] = accsp[0][nl][a][f] + accsp[1][nl][a][f];
    float4 d0 = *(const float4*)&g_Dinv[i * 16 + (2 * h) * 4];
    float4 d1 = *(const float4*)&g_Dinv[i * 16 + (2 * h + 1) * 4];
    float sh0 = fmaf(d0.x, ac[0], fmaf(d0.y, ac[1], fmaf(d0.z, ac[2], d0.w * ac[3])));
    float sh1 = fmaf(d1.x, ac[0], fmaf(d1.y, ac[1], fmaf(d1.z, ac[2], d1.w * ac[3])));

    float4 pr = g_P4[i * 64 + f];
    float pr0 = (h == 0) ? pr.x : pr.z;
    float pr1 = (h == 0) ? pr.y : pr.w;
    float sb = 1.f / (1.f + expf(-beta[0]));
    float e0 = (sh0 > 0.f) ? sh0 : expm1f(sh0);
    float e1 = (sh1 > 0.f) ? sh1 : expm1f(sh1);
    out[(4 * i + 2 * h) * 64 + f]     = pr0 - sb * e0;
    out[(4 * i + 2 * h + 1) * 64 + f] = pr1 - sb * e1;
}

extern "C" void kernel_launch(void* const* d_in, const int* in_sizes, int n_in,
                              void* d_out, int out_size) {
    const float* ef    = (const float*)d_in[0];
    const float* L1    = (const float*)d_in[1];
    const float* X     = (const float*)d_in[2];
    const float* W1    = (const float*)d_in[3];
    const float* b1    = (const float*)d_in[4];
    const float* W2    = (const float*)d_in[5];
    const float* b2    = (const float*)d_in[6];
    const float* W3    = (const float*)d_in[7];
    const float* b3    = (const float*)d_in[8];
    const float* Wh    = (const float*)d_in[9];
    const float* Ws1   = (const float*)d_in[10];
    const float* Ws2   = (const float*)d_in[11];
    const float* resW  = (const float*)d_in[12];
    const float* resb  = (const float*)d_in[13];
    const float* alpha = (const float*)d_in[14];
    const float* beta  = (const float*)d_in[15];
    const int*   eidx  = (const int*)d_in[16];
    const int*   jiidx = (const int*)d_in[17];
    float* out = (float*)d_out;

    k_pre<<<512, 256>>>(ef, W1, b1, X, Ws1, Ws2);
    k_pair<<<1024, 256>>>(L1, W2, b2, W3, b3, eidx);
    k_mid<<<512, 256>>>(eidx, jiidx, Wh, X, resW, resb, alpha);
    k_out<<<512, 512>>>(eidx, beta, out);
}

// round 16
// speedup vs baseline: 1.0763x; 1.0378x over previous
#include <cuda_runtime.h>
#include <cuda_bf16.h>
#include <math.h>

#define NE 2048
#define NP 32768

// ---------------- static device scratch ----------------
__device__ float g_U[NE * 64];
__device__ float g_V[NE * 64];
__device__ float g_R[NP * 16];
__device__ float4 g_off4[NP * 4];
__device__ float g_lvals[NP];
__device__ float g_diag[NE * 16];
__device__ float g_Dinv[NE * 16];
__device__ float4 g_Z4[NE * 64];
__device__ float4 g_Xt4[NE * 64];
__device__ float4 g_P4[NE * 64];
__device__ float g_Xcol[NE * 64];

// ---------------- K0: U, V, Xcol, Xt (R11 winner) -----------------------
__global__ void k_pre(const float* __restrict__ ef, const float* __restrict__ W1,
                      const float* __restrict__ b1, const float* __restrict__ X,
                      const float* __restrict__ Ws1, const float* __restrict__ Ws2) {
    int nl = threadIdx.x >> 6, f = threadIdx.x & 63;
    int n = blockIdx.x * 4 + nl;
    __shared__ float efs[4][64];
    __shared__ float Ysh[4][4][64];
    efs[nl][f] = ef[n * 64 + f];
    float xr[4];
    #pragma unroll
    for (int b = 0; b < 4; b++) xr[b] = X[(4 * n + b) * 64 + f];
    g_Xcol[n * 64 + f] = 0.25f * (xr[0] + xr[1] + xr[2] + xr[3]);
    #pragma unroll
    for (int a = 0; a < 4; a++) {
        float y = 0.f;
        #pragma unroll
        for (int b = 0; b < 4; b++) y = fmaf(Ws1[a * 4 + b], xr[b], y);
        Ysh[nl][a][f] = y;
    }
    __syncthreads();
    float u = b1[f], v = 0.f;
    #pragma unroll 8
    for (int k = 0; k < 64; k++) {
        float x = efs[nl][k];
        u = fmaf(x, W1[k * 64 + f], u);
        v = fmaf(x, W1[(64 + k) * 64 + f], v);
    }
    g_U[n * 64 + f] = u;
    g_V[n * 64 + f] = v;
    float xt[4] = {0.f, 0.f, 0.f, 0.f};
    #pragma unroll 4
    for (int g = 0; g < 64; g++) {
        float w2 = Ws2[g * 64 + f];
        #pragma unroll
        for (int a = 0; a < 4; a++) xt[a] = fmaf(Ysh[nl][a][g], w2, xt[a]);
    }
    float4 o;
    o.x = xt[0]; o.y = xt[1]; o.z = xt[2]; o.w = xt[3];
    g_Xt4[n * 64 + f] = o;
#if __CUDA_ARCH__ >= 900
    cudaTriggerProgrammaticLaunchCompletion();
#endif
}

// ---------------- K1: MLP tail -> R (R11 + PDL prologue) ----------------
__global__ void k_pair(const float* __restrict__ L1,
                       const float* __restrict__ W2, const float* __restrict__ b2,
                       const float* __restrict__ W3, const float* __restrict__ b3,
                       const int* __restrict__ eidx) {
    __shared__ float W2s[64 * 32];
    __shared__ float W3s[32 * 16];
    __shared__ float b2s[32], b3s[16];
    int tid = threadIdx.x;
    // ---- prologue: inputs only (W2/W3/b2/b3, eidx, L1) ----
    for (int i = tid; i < 64 * 32; i += 256) W2s[i] = W2[i];
    for (int i = tid; i < 32 * 16; i += 256) W3s[i] = W3[i];
    if (tid < 32) b2s[tid] = b2[tid];
    if (tid < 16) b3s[tid] = b3[tid];
    int w = tid >> 5, lane = tid & 31;
    int gw = blockIdx.x * 8 + w;
    int p0 = gw * 8;
    if (lane < 8) {
        int p = p0 + lane;
        int ii = eidx[2 * p], jj = eidx[2 * p + 1];
        g_lvals[p] = L1[(size_t)ii * NE + jj];
    }
    __syncthreads();
#if __CUDA_ARCH__ >= 900
    cudaGridDependencySynchronize();   // wait for k_pre's U/V
#endif

    float hx[8], hy[8];
    #pragma unroll
    for (int pi = 0; pi < 8; pi++) {
        int p = p0 + pi;
        int ii = eidx[2 * p], jj = eidx[2 * p + 1];
        float2 uu = *(const float2*)&g_U[ii * 64 + 2 * lane];
        float2 vv = *(const float2*)&g_V[jj * 64 + 2 * lane];
        hx[pi] = fmaxf(uu.x + vv.x, 0.f);
        hy[pi] = fmaxf(uu.y + vv.y, 0.f);
    }

    float c[8];
    float b2v = b2s[lane];
    #pragma unroll
    for (int pi = 0; pi < 8; pi++) c[pi] = b2v;
    #pragma unroll
    for (int k = 0; k < 64; k++) {
        float wv = W2s[k * 32 + lane];
        int src = k >> 1;
        #pragma unroll
        for (int pi = 0; pi < 8; pi++) {
            float hval = __shfl_sync(0xffffffffu, (k & 1) ? hy[pi] : hx[pi], src);
            c[pi] = fmaf(hval, wv, c[pi]);
        }
    }
    #pragma unroll
    for (int pi = 0; pi < 8; pi++) c[pi] = fmaxf(c[pi], 0.f);

    float r[8];
    float b3v = (lane < 16) ? b3s[lane] : 0.f;
    #pragma unroll
    for (int pi = 0; pi < 8; pi++) r[pi] = b3v;
    #pragma unroll
    for (int k = 0; k < 32; k++) {
        float wv = (lane < 16) ? W3s[k * 16 + lane] : 0.f;
        #pragma unroll
        for (int pi = 0; pi < 8; pi++) {
            float hval = __shfl_sync(0xffffffffu, c[pi], k);
            r[pi] = fmaf(hval, wv, r[pi]);
        }
    }
    if (lane < 16) {
        #pragma unroll
        for (int pi = 0; pi < 8; pi++)
            g_R[(p0 + pi) * 16 + lane] = r[pi];
    }
#if __CUDA_ARCH__ >= 900
    cudaTriggerProgrammaticLaunchCompletion();
#endif
}

// ---------------- K2: diag/Jacobi/off + Z + hodge + residual (R11+PDL) --
__global__ void k_mid(const int* __restrict__ eidx, const int* __restrict__ jiidx,
                      const float* __restrict__ Wh, const float* __restrict__ X,
                      const float* __restrict__ resW, const float* __restrict__ resb,
                      const float* __restrict__ alpha) {
    __shared__ float sDb[4][16];
    __shared__ float sDinv[4][16];
    __shared__ float Xcw[20][64];
    __shared__ float Xsh[4][4][64];
    __shared__ float hps[4][64];
    __shared__ int jrel[4][16];
    __shared__ float lv[4][16];
    int tid = threadIdx.x;
    int w = tid >> 5, lane = tid & 31;
    int i0 = blockIdx.x * 4;

    // ---- prologue: inputs only (X rows, eidx meta) ----
    #pragma unroll
    for (int t = 0; t < 4; t++) {
        int idx = tid + t * 256;
        int nn = idx >> 8, rest = idx & 255;
        int b = rest >> 6, ff = rest & 63;
        Xsh[nn][b][ff] = X[(4 * (i0 + nn) + b) * 64 + ff];
    }
    if (tid < 64) {
        int nn = tid >> 4, k = tid & 15;
        int pp = (i0 + nn) * 16 + k;
        int j = eidx[2 * pp + 1];
        jrel[nn][k] = (j - i0 + 8) & (NE - 1);
    }
#if __CUDA_ARCH__ >= 900
    cudaGridDependencySynchronize();   // wait for k_pair's R / lvals (and earlier)
#endif

    if (w < 4) {
        int node = i0 + w;
        float Fm[16];
        #pragma unroll
        for (int x = 0; x < 16; x++) Fm[x] = 0.f;
        if (lane < 16) {
            int p = node * 16 + lane;
            float4 r0 = *(const float4*)&g_R[p * 16];
            float4 r1 = *(const float4*)&g_R[p * 16 + 4];
            float4 r2 = *(const float4*)&g_R[p * 16 + 8];
            float4 r3 = *(const float4*)&g_R[p * 16 + 12];
            float Rv[16] = {r0.x, r0.y, r0.z, r0.w, r1.x, r1.y, r1.z, r1.w,
                            r2.x, r2.y, r2.z, r2.w, r3.x, r3.y, r3.z, r3.w};
            #pragma unroll
            for (int a = 0; a < 4; a++)
                #pragma unroll
                for (int b = 0; b < 4; b++) {
                    float s = 0.f;
                    #pragma unroll
                    for (int c = 0; c < 4; c++) s = fmaf(Rv[c * 4 + a], Rv[c * 4 + b], s);
                    Fm[a * 4 + b] = s;
                }
        }
        #pragma unroll
        for (int x = 0; x < 16; x++) {
            Fm[x] += __shfl_down_sync(0xffffffffu, Fm[x], 8);
            Fm[x] += __shfl_down_sync(0xffffffffu, Fm[x], 4);
            Fm[x] += __shfl_down_sync(0xffffffffu, Fm[x], 2);
            Fm[x] += __shfl_down_sync(0xffffffffu, Fm[x], 1);
        }
        if (lane == 0) {
            #pragma unroll
            for (int x = 0; x < 16; x++) { sDb[w][x] = Fm[x]; g_diag[node * 16 + x] = Fm[x]; }
        }
    }
    __syncthreads();

    if (tid < 64) {
        int p = i0 * 16 + tid;
        int jp = jiidx[p];
        float l = g_lvals[p];
        float msg = (l > 0.f) ? -1.f : ((l < 0.f) ? 1.f : 0.f);
        float4 a0 = *(const float4*)&g_R[jp * 16];
        float4 a1 = *(const float4*)&g_R[jp * 16 + 4];
        float4 a2 = *(const float4*)&g_R[jp * 16 + 8];
        float4 a3 = *(const float4*)&g_R[jp * 16 + 12];
        float4 b0 = *(const float4*)&g_R[p * 16];
        float4 b1v = *(const float4*)&g_R[p * 16 + 4];
        float4 b2v = *(const float4*)&g_R[p * 16 + 8];
        float4 b3v = *(const float4*)&g_R[p * 16 + 12];
        float Ra[16] = {a0.x, a0.y, a0.z, a0.w, a1.x, a1.y, a1.z, a1.w,
                        a2.x, a2.y, a2.z, a2.w, a3.x, a3.y, a3.z, a3.w};
        float Rb[16] = {b0.x, b0.y, b0.z, b0.w, b1v.x, b1v.y, b1v.z, b1v.w,
                        b2v.x, b2v.y, b2v.z, b2v.w, b3v.x, b3v.y, b3v.z, b3v.w};
        #pragma unroll
        for (int a = 0; a < 4; a++) {
            float4 row;
            float* rp = (float*)&row;
            #pragma unroll
            for (int b = 0; b < 4; b++) {
                float m = 0.f;
                #pragma unroll
                for (int c = 0; c < 4; c++) m = fmaf(Ra[c * 4 + a], Rb[c * 4 + b], m);
                rp[b] = msg * m;
            }
            g_off4[p * 4 + a] = row;
        }
    } else if (tid < 68) {
        int nl = tid - 64;
        const float eps = 1e-4f;
        float A[4][4], V[4][4];
        #pragma unroll
        for (int a = 0; a < 4; a++)
            #pragma unroll
            for (int b = 0; b < 4; b++) {
                A[a][b] = 0.5f * (sDb[nl][a * 4 + b] + sDb[nl][b * 4 + a]);
                V[a][b] = (a == b) ? 1.f : 0.f;
            }
        #pragma unroll
        for (int a = 0; a < 4; a++) A[a][a] += eps;
        const int PI[6] = {0, 0, 0, 1, 1, 2};
        const int QI[6] = {1, 2, 3, 2, 3, 3};
        #pragma unroll
        for (int sweep = 0; sweep < 6; sweep++) {
            #pragma unroll
            for (int r = 0; r < 6; r++) {
                int p = PI[r], q = QI[r];
                float apq = A[p][q];
                if (fabsf(apq) > 1e-20f) {
                    float theta = (A[q][q] - A[p][p]) / (2.f * apq);
                    float t = copysignf(1.f, theta) / (fabsf(theta) + sqrtf(theta * theta + 1.f));
                    float cth = rsqrtf(t * t + 1.f);
                    float sth = t * cth;
                    float app = A[p][p], aqq = A[q][q];
                    A[p][p] = app - t * apq;
                    A[q][q] = aqq + t * apq;
                    A[p][q] = 0.f; A[q][p] = 0.f;
                    #pragma unroll
                    for (int k = 0; k < 4; k++) {
                        if (k != p && k != q) {
                            float akp = A[k][p], akq = A[k][q];
                            A[k][p] = cth * akp - sth * akq; A[p][k] = A[k][p];
                            A[k][q] = sth * akp + cth * akq; A[q][k] = A[k][q];
                        }
                    }
                    #pragma unroll
                    for (int k = 0; k < 4; k++) {
                        float vkp = V[k][p], vkq = V[k][q];
                        V[k][p] = cth * vkp - sth * vkq;
                        V[k][q] = sth * vkp + cth * vkq;
                    }
                }
            }
        }
        float invs[4];
        #pragma unroll
        for (int k = 0; k < 4; k++) invs[k] = rsqrtf(fmaxf(A[k][k], eps));
        int gnode = i0 + nl;
        #pragma unroll
        for (int a = 0; a < 4; a++)
            #pragma unroll
            for (int b = 0; b < 4; b++) {
                float s = 0.f;
                #pragma unroll
                for (int k = 0; k < 4; k++) s = fmaf(V[a][k] * invs[k], V[b][k], s);
                sDinv[nl][a * 4 + b] = s;
                g_Dinv[gnode * 16 + a * 4 + b] = s;
            }
    }

    #pragma unroll
    for (int t = 0; t < 5; t++) {
        int idx = tid + t * 256;
        int row = idx >> 6, ff = idx & 63;
        int src = (i0 - 8 + row) & (NE - 1);
        Xcw[row][ff] = g_Xcol[src * 64 + ff];
    }
    if (tid < 64) {
        int nn = tid >> 4, k = tid & 15;
        lv[nn][k] = fabsf(g_lvals[(i0 + nn) * 16 + k]);
    }
    __syncthreads();

    int nl = tid >> 6, f = tid & 63;
    int n = i0 + nl;

    {
        float4 xt = g_Xt4[n * 64 + f];
        float dv[16];
        #pragma unroll
        for (int x = 0; x < 16; x++) dv[x] = sDinv[nl][x];
        float4 z;
        z.x = fmaf(dv[0], xt.x, fmaf(dv[1], xt.y, fmaf(dv[2], xt.z, dv[3] * xt.w)));
        z.y = fmaf(dv[4], xt.x, fmaf(dv[5], xt.y, fmaf(dv[6], xt.z, dv[7] * xt.w)));
        z.z = fmaf(dv[8], xt.x, fmaf(dv[9], xt.y, fmaf(dv[10], xt.z, dv[11] * xt.w)));
        z.w = fmaf(dv[12], xt.x, fmaf(dv[13], xt.y, fmaf(dv[14], xt.z, dv[15] * xt.w)));
        g_Z4[n * 64 + f] = z;
    }

    float s = 0.f;
    #pragma unroll
    for (int p = 0; p < 16; p++) s += lv[nl][p];
    float inv = 1.f / (s + 1e-8f);
    float hp = Xcw[8 + nl][f];
    #pragma unroll
    for (int p = 0; p < 16; p++)
        hp = fmaf(lv[nl][p] * inv, Xcw[jrel[nl][p]][f], hp);
    hps[nl][f] = hp;
    __syncthreads();
    float h = 0.f;
    #pragma unroll 4
    for (int g = 0; g < 64; g++) h = fmaf(hps[nl][g], Wh[g * 64 + f], h);
    float sa = 1.f / (1.f + expf(-alpha[0]));
    float bb = resb[f];
    float r[4];
    #pragma unroll
    for (int b = 0; b < 4; b++) r[b] = bb;
    #pragma unroll 4
    for (int k = 0; k < 64; k++) {
        float wv = resW[k * 64 + f];
        #pragma unroll
        for (int b = 0; b < 4; b++) r[b] = fmaf(Xsh[nl][b][k], wv, r[b]);
    }
    float4 pr;
    pr.x = r[0] - sa * h; pr.y = r[1] - sa * h;
    pr.z = r[2] - sa * h; pr.w = r[3] - sa * h;
    g_P4[n * 64 + f] = pr;
#if __CUDA_ARCH__ >= 900
    cudaTriggerProgrammaticLaunchCompletion();
#endif
}

// ---------------- K3: sheaf + combine (R11 + PDL) -----------------------
__global__ void k_out(const int* __restrict__ eidx, const float* __restrict__ beta,
                      float* __restrict__ out) {
    int tid = threadIdx.x;
    int nl = tid >> 6, f = tid & 63;
    int i0 = blockIdx.x * 4;
    int i = i0 + nl;
    __shared__ float4 Z4sh[20][64];
    __shared__ float4 offs4[4][64];
    __shared__ int jrel[4][16];

    // ---- prologue: inputs only ----
    if (f < 16) {
        int pp = 16 * i + f;
        int j = eidx[2 * pp + 1];
        jrel[nl][f] = (j - i0 + 8) & (NE - 1);
    }
#if __CUDA_ARCH__ >= 900
    cudaGridDependencySynchronize();   // wait for k_mid's Z4/off4/P4
#endif

    #pragma unroll
    for (int t = 0; t < 5; t++) {
        int idx = tid + t * 256;
        int row = idx >> 6, ff = idx & 63;
        int src = (i0 - 8 + row) & (NE - 1);
        Z4sh[row][ff] = g_Z4[src * 64 + ff];
    }
    offs4[nl][f] = g_off4[i * 64 + f];
    __syncthreads();

    float4 zi = Z4sh[8 + nl][f];
    const float4* dgr = (const float4*)&g_diag[i * 16];
    float accs[4];
    #pragma unroll
    for (int a = 0; a < 4; a++) {
        float4 d = dgr[a];
        accs[a] = fmaf(d.x, zi.x, fmaf(d.y, zi.y, fmaf(d.z, zi.z, d.w * zi.w)));
    }
    #pragma unroll
    for (int k = 0; k < 16; k++) {
        float4 zj = Z4sh[jrel[nl][k]][f];
        #pragma unroll
        for (int a = 0; a < 4; a++) {
            float4 o = offs4[nl][k * 4 + a];
            accs[a] = fmaf(o.x, zj.x, fmaf(o.y, zj.y, fmaf(o.z, zj.z, fmaf(o.w, zj.w, accs[a]))));
        }
    }
    const float4* dvr = (const float4*)&g_Dinv[i * 16];
    float sh[4];
    #pragma unroll
    for (int a = 0; a < 4; a++) {
        float4 d = dvr[a];
        sh[a] = fmaf(d.x, accs[0], fmaf(d.y, accs[1], fmaf(d.z, accs[2], d.w * accs[3])));
    }

    float4 pr = g_P4[i * 64 + f];
    float sb = 1.f / (1.f + expf(-beta[0]));
    float prr[4] = {pr.x, pr.y, pr.z, pr.w};
    #pragma unroll
    for (int b = 0; b < 4; b++) {
        float e = (sh[b] > 0.f) ? sh[b] : expm1f(sh[b]);
        out[(4 * i + b) * 64 + f] = prr[b] - sb * e;
    }
}

extern "C" void kernel_launch(void* const* d_in, const int* in_sizes, int n_in,
                              void* d_out, int out_size) {
    const float* ef    = (const float*)d_in[0];
    const float* L1    = (const float*)d_in[1];
    const float* X     = (const float*)d_in[2];
    const float* W1    = (const float*)d_in[3];
    const float* b1    = (const float*)d_in[4];
    const float* W2    = (const float*)d_in[5];
    const float* b2    = (const float*)d_in[6];
    const float* W3    = (const float*)d_in[7];
    const float* b3    = (const float*)d_in[8];
    const float* Wh    = (const float*)d_in[9];
    const float* Ws1   = (const float*)d_in[10];
    const float* Ws2   = (const float*)d_in[11];
    const float* resW  = (const float*)d_in[12];
    const float* resb  = (const float*)d_in[13];
    const float* alpha = (const float*)d_in[14];
    const float* beta  = (const float*)d_in[15];
    const int*   eidx  = (const int*)d_in[16];
    const int*   jiidx = (const int*)d_in[17];
    float* out = (float*)d_out;

    k_pre<<<512, 256>>>(ef, W1, b1, X, Ws1, Ws2);

    cudaLaunchAttribute attr[1];
    attr[0].id = cudaLaunchAttributeProgrammaticStreamSerialization;
    attr[0].val.programmaticStreamSerializationAllowed = 1;

    cudaLaunchConfig_t cfg = {};
    cfg.gridDim = dim3(512, 1, 1);
    cfg.blockDim = dim3(256, 1, 1);
    cfg.stream = 0;
    cfg.attrs = attr;
    cfg.numAttrs = 1;

    cudaLaunchKernelEx(&cfg, k_pair, L1, W2, b2, W3, b3, eidx);
    cudaLaunchKernelEx(&cfg, k_mid, eidx, jiidx, Wh, X, resW, resb, alpha);
    cudaLaunchKernelEx(&cfg, k_out, eidx, beta, out);
}

// round 17
// speedup vs baseline: 1.0769x; 1.0006x over previous
#include <cuda_runtime.h>
#include <cuda_bf16.h>
#include <math.h>

#define NE 2048
#define NP 32768

// ---------------- static device scratch ----------------
__device__ float g_U[NE * 64];
__device__ float g_V[NE * 64];
__device__ float g_R[NP * 16];
__device__ float4 g_off4[NP * 4];
__device__ float g_lvals[NP];
__device__ float g_diag[NE * 16];
__device__ float g_Dinv[NE * 16];
__device__ float4 g_Z4[NE * 64];
__device__ float4 g_Xt4[NE * 64];
__device__ float4 g_P4[NE * 64];
__device__ float g_Xcol[NE * 64];

// ---------------- K0: U, V, Xcol, Xt (R11 winner) -----------------------
__global__ void k_pre(const float* __restrict__ ef, const float* __restrict__ W1,
                      const float* __restrict__ b1, const float* __restrict__ X,
                      const float* __restrict__ Ws1, const float* __restrict__ Ws2) {
    int nl = threadIdx.x >> 6, f = threadIdx.x & 63;
    int n = blockIdx.x * 4 + nl;
    __shared__ float efs[4][64];
    __shared__ float Ysh[4][4][64];
    efs[nl][f] = ef[n * 64 + f];
    float xr[4];
    #pragma unroll
    for (int b = 0; b < 4; b++) xr[b] = X[(4 * n + b) * 64 + f];
    g_Xcol[n * 64 + f] = 0.25f * (xr[0] + xr[1] + xr[2] + xr[3]);
    #pragma unroll
    for (int a = 0; a < 4; a++) {
        float y = 0.f;
        #pragma unroll
        for (int b = 0; b < 4; b++) y = fmaf(Ws1[a * 4 + b], xr[b], y);
        Ysh[nl][a][f] = y;
    }
    __syncthreads();
    float u = b1[f], v = 0.f;
    #pragma unroll 8
    for (int k = 0; k < 64; k++) {
        float x = efs[nl][k];
        u = fmaf(x, W1[k * 64 + f], u);
        v = fmaf(x, W1[(64 + k) * 64 + f], v);
    }
    g_U[n * 64 + f] = u;
    g_V[n * 64 + f] = v;
    float xt[4] = {0.f, 0.f, 0.f, 0.f};
    #pragma unroll 4
    for (int g = 0; g < 64; g++) {
        float w2 = Ws2[g * 64 + f];
        #pragma unroll
        for (int a = 0; a < 4; a++) xt[a] = fmaf(Ysh[nl][a][g], w2, xt[a]);
    }
    float4 o;
    o.x = xt[0]; o.y = xt[1]; o.z = xt[2]; o.w = xt[3];
    g_Xt4[n * 64 + f] = o;
#if __CUDA_ARCH__ >= 900
    cudaTriggerProgrammaticLaunchCompletion();
#endif
}

// ---------------- K1: MLP tail -> R (R11 + PDL prologue) ----------------
__global__ void k_pair(const float* __restrict__ L1,
                       const float* __restrict__ W2, const float* __restrict__ b2,
                       const float* __restrict__ W3, const float* __restrict__ b3,
                       const int* __restrict__ eidx) {
    __shared__ float W2s[64 * 32];
    __shared__ float W3s[32 * 16];
    __shared__ float b2s[32], b3s[16];
    int tid = threadIdx.x;
    for (int i = tid; i < 64 * 32; i += 256) W2s[i] = W2[i];
    for (int i = tid; i < 32 * 16; i += 256) W3s[i] = W3[i];
    if (tid < 32) b2s[tid] = b2[tid];
    if (tid < 16) b3s[tid] = b3[tid];
    int w = tid >> 5, lane = tid & 31;
    int gw = blockIdx.x * 8 + w;
    int p0 = gw * 8;
    if (lane < 8) {
        int p = p0 + lane;
        int ii = eidx[2 * p], jj = eidx[2 * p + 1];
        g_lvals[p] = L1[(size_t)ii * NE + jj];
    }
    __syncthreads();
#if __CUDA_ARCH__ >= 900
    cudaGridDependencySynchronize();
#endif

    float hx[8], hy[8];
    #pragma unroll
    for (int pi = 0; pi < 8; pi++) {
        int p = p0 + pi;
        int ii = eidx[2 * p], jj = eidx[2 * p + 1];
        float2 uu = *(const float2*)&g_U[ii * 64 + 2 * lane];
        float2 vv = *(const float2*)&g_V[jj * 64 + 2 * lane];
        hx[pi] = fmaxf(uu.x + vv.x, 0.f);
        hy[pi] = fmaxf(uu.y + vv.y, 0.f);
    }

    float c[8];
    float b2v = b2s[lane];
    #pragma unroll
    for (int pi = 0; pi < 8; pi++) c[pi] = b2v;
    #pragma unroll
    for (int k = 0; k < 64; k++) {
        float wv = W2s[k * 32 + lane];
        int src = k >> 1;
        #pragma unroll
        for (int pi = 0; pi < 8; pi++) {
            float hval = __shfl_sync(0xffffffffu, (k & 1) ? hy[pi] : hx[pi], src);
            c[pi] = fmaf(hval, wv, c[pi]);
        }
    }
    #pragma unroll
    for (int pi = 0; pi < 8; pi++) c[pi] = fmaxf(c[pi], 0.f);

    float r[8];
    float b3v = (lane < 16) ? b3s[lane] : 0.f;
    #pragma unroll
    for (int pi = 0; pi < 8; pi++) r[pi] = b3v;
    #pragma unroll
    for (int k = 0; k < 32; k++) {
        float wv = (lane < 16) ? W3s[k * 16 + lane] : 0.f;
        #pragma unroll
        for (int pi = 0; pi < 8; pi++) {
            float hval = __shfl_sync(0xffffffffu, c[pi], k);
            r[pi] = fmaf(hval, wv, r[pi]);
        }
    }
    if (lane < 16) {
        #pragma unroll
        for (int pi = 0; pi < 8; pi++)
            g_R[(p0 + pi) * 16 + lane] = r[pi];
    }
#if __CUDA_ARCH__ >= 900
    cudaTriggerProgrammaticLaunchCompletion();
#endif
}

// ---------------- K2: diag/Jacobi/off + Z + hodge + residual (R16) ------
__global__ void k_mid(const int* __restrict__ eidx, const int* __restrict__ jiidx,
                      const float* __restrict__ Wh, const float* __restrict__ X,
                      const float* __restrict__ resW, const float* __restrict__ resb,
                      const float* __restrict__ alpha) {
    __shared__ float sDb[4][16];
    __shared__ float sDinv[4][16];
    __shared__ float Xcw[20][64];
    __shared__ float Xsh[4][4][64];
    __shared__ float hps[4][64];
    __shared__ int jrel[4][16];
    __shared__ float lv[4][16];
    int tid = threadIdx.x;
    int w = tid >> 5, lane = tid & 31;
    int i0 = blockIdx.x * 4;

    #pragma unroll
    for (int t = 0; t < 4; t++) {
        int idx = tid + t * 256;
        int nn = idx >> 8, rest = idx & 255;
        int b = rest >> 6, ff = rest & 63;
        Xsh[nn][b][ff] = X[(4 * (i0 + nn) + b) * 64 + ff];
    }
    if (tid < 64) {
        int nn = tid >> 4, k = tid & 15;
        int pp = (i0 + nn) * 16 + k;
        int j = eidx[2 * pp + 1];
        jrel[nn][k] = (j - i0 + 8) & (NE - 1);
    }
#if __CUDA_ARCH__ >= 900
    cudaGridDependencySynchronize();
#endif

    if (w < 4) {
        int node = i0 + w;
        float Fm[16];
        #pragma unroll
        for (int x = 0; x < 16; x++) Fm[x] = 0.f;
        if (lane < 16) {
            int p = node * 16 + lane;
            float4 r0 = *(const float4*)&g_R[p * 16];
            float4 r1 = *(const float4*)&g_R[p * 16 + 4];
            float4 r2 = *(const float4*)&g_R[p * 16 + 8];
            float4 r3 = *(const float4*)&g_R[p * 16 + 12];
            float Rv[16] = {r0.x, r0.y, r0.z, r0.w, r1.x, r1.y, r1.z, r1.w,
                            r2.x, r2.y, r2.z, r2.w, r3.x, r3.y, r3.z, r3.w};
            #pragma unroll
            for (int a = 0; a < 4; a++)
                #pragma unroll
                for (int b = 0; b < 4; b++) {
                    float s = 0.f;
                    #pragma unroll
                    for (int c = 0; c < 4; c++) s = fmaf(Rv[c * 4 + a], Rv[c * 4 + b], s);
                    Fm[a * 4 + b] = s;
                }
        }
        #pragma unroll
        for (int x = 0; x < 16; x++) {
            Fm[x] += __shfl_down_sync(0xffffffffu, Fm[x], 8);
            Fm[x] += __shfl_down_sync(0xffffffffu, Fm[x], 4);
            Fm[x] += __shfl_down_sync(0xffffffffu, Fm[x], 2);
            Fm[x] += __shfl_down_sync(0xffffffffu, Fm[x], 1);
        }
        if (lane == 0) {
            #pragma unroll
            for (int x = 0; x < 16; x++) { sDb[w][x] = Fm[x]; g_diag[node * 16 + x] = Fm[x]; }
        }
    }
    __syncthreads();

    if (tid < 64) {
        int p = i0 * 16 + tid;
        int jp = jiidx[p];
        float l = g_lvals[p];
        float msg = (l > 0.f) ? -1.f : ((l < 0.f) ? 1.f : 0.f);
        float4 a0 = *(const float4*)&g_R[jp * 16];
        float4 a1 = *(const float4*)&g_R[jp * 16 + 4];
        float4 a2 = *(const float4*)&g_R[jp * 16 + 8];
        float4 a3 = *(const float4*)&g_R[jp * 16 + 12];
        float4 b0 = *(const float4*)&g_R[p * 16];
        float4 b1v = *(const float4*)&g_R[p * 16 + 4];
        float4 b2v = *(const float4*)&g_R[p * 16 + 8];
        float4 b3v = *(const float4*)&g_R[p * 16 + 12];
        float Ra[16] = {a0.x, a0.y, a0.z, a0.w, a1.x, a1.y, a1.z, a1.w,
                        a2.x, a2.y, a2.z, a2.w, a3.x, a3.y, a3.z, a3.w};
        float Rb[16] = {b0.x, b0.y, b0.z, b0.w, b1v.x, b1v.y, b1v.z, b1v.w,
                        b2v.x, b2v.y, b2v.z, b2v.w, b3v.x, b3v.y, b3v.z, b3v.w};
        #pragma unroll
        for (int a = 0; a < 4; a++) {
            float4 row;
            float* rp = (float*)&row;
            #pragma unroll
            for (int b = 0; b < 4; b++) {
                float m = 0.f;
                #pragma unroll
                for (int c = 0; c < 4; c++) m = fmaf(Ra[c * 4 + a], Rb[c * 4 + b], m);
                rp[b] = msg * m;
            }
            g_off4[p * 4 + a] = row;
        }
    } else if (tid < 68) {
        int nl = tid - 64;
        const float eps = 1e-4f;
        float A[4][4], V[4][4];
        #pragma unroll
        for (int a = 0; a < 4; a++)
            #pragma unroll
            for (int b = 0; b < 4; b++) {
                A[a][b] = 0.5f * (sDb[nl][a * 4 + b] + sDb[nl][b * 4 + a]);
                V[a][b] = (a == b) ? 1.f : 0.f;
            }
        #pragma unroll
        for (int a = 0; a < 4; a++) A[a][a] += eps;
        const int PI[6] = {0, 0, 0, 1, 1, 2};
        const int QI[6] = {1, 2, 3, 2, 3, 3};
        #pragma unroll
        for (int sweep = 0; sweep < 6; sweep++) {
            #pragma unroll
            for (int r = 0; r < 6; r++) {
                int p = PI[r], q = QI[r];
                float apq = A[p][q];
                if (fabsf(apq) > 1e-20f) {
                    float theta = (A[q][q] - A[p][p]) / (2.f * apq);
                    float t = copysignf(1.f, theta) / (fabsf(theta) + sqrtf(theta * theta + 1.f));
                    float cth = rsqrtf(t * t + 1.f);
                    float sth = t * cth;
                    float app = A[p][p], aqq = A[q][q];
                    A[p][p] = app - t * apq;
                    A[q][q] = aqq + t * apq;
                    A[p][q] = 0.f; A[q][p] = 0.f;
                    #pragma unroll
                    for (int k = 0; k < 4; k++) {
                        if (k != p && k != q) {
                            float akp = A[k][p], akq = A[k][q];
                            A[k][p] = cth * akp - sth * akq; A[p][k] = A[k][p];
                            A[k][q] = sth * akp + cth * akq; A[q][k] = A[k][q];
                        }
                    }
                    #pragma unroll
                    for (int k = 0; k < 4; k++) {
                        float vkp = V[k][p], vkq = V[k][q];
                        V[k][p] = cth * vkp - sth * vkq;
                        V[k][q] = sth * vkp + cth * vkq;
                    }
                }
            }
        }
        float invs[4];
        #pragma unroll
        for (int k = 0; k < 4; k++) invs[k] = rsqrtf(fmaxf(A[k][k], eps));
        int gnode = i0 + nl;
        #pragma unroll
        for (int a = 0; a < 4; a++)
            #pragma unroll
            for (int b = 0; b < 4; b++) {
                float s = 0.f;
                #pragma unroll
                for (int k = 0; k < 4; k++) s = fmaf(V[a][k] * invs[k], V[b][k], s);
                sDinv[nl][a * 4 + b] = s;
                g_Dinv[gnode * 16 + a * 4 + b] = s;
            }
    }

    #pragma unroll
    for (int t = 0; t < 5; t++) {
        int idx = tid + t * 256;
        int row = idx >> 6, ff = idx & 63;
        int src = (i0 - 8 + row) & (NE - 1);
        Xcw[row][ff] = g_Xcol[src * 64 + ff];
    }
    if (tid < 64) {
        int nn = tid >> 4, k = tid & 15;
        lv[nn][k] = fabsf(g_lvals[(i0 + nn) * 16 + k]);
    }
    __syncthreads();

    int nl = tid >> 6, f = tid & 63;
    int n = i0 + nl;

    {
        float4 xt = g_Xt4[n * 64 + f];
        float dv[16];
        #pragma unroll
        for (int x = 0; x < 16; x++) dv[x] = sDinv[nl][x];
        float4 z;
        z.x = fmaf(dv[0], xt.x, fmaf(dv[1], xt.y, fmaf(dv[2], xt.z, dv[3] * xt.w)));
        z.y = fmaf(dv[4], xt.x, fmaf(dv[5], xt.y, fmaf(dv[6], xt.z, dv[7] * xt.w)));
        z.z = fmaf(dv[8], xt.x, fmaf(dv[9], xt.y, fmaf(dv[10], xt.z, dv[11] * xt.w)));
        z.w = fmaf(dv[12], xt.x, fmaf(dv[13], xt.y, fmaf(dv[14], xt.z, dv[15] * xt.w)));
        g_Z4[n * 64 + f] = z;
    }

    float s = 0.f;
    #pragma unroll
    for (int p = 0; p < 16; p++) s += lv[nl][p];
    float inv = 1.f / (s + 1e-8f);
    float hp = Xcw[8 + nl][f];
    #pragma unroll
    for (int p = 0; p < 16; p++)
        hp = fmaf(lv[nl][p] * inv, Xcw[jrel[nl][p]][f], hp);
    hps[nl][f] = hp;
    __syncthreads();
    float h = 0.f;
    #pragma unroll 4
    for (int g = 0; g < 64; g++) h = fmaf(hps[nl][g], Wh[g * 64 + f], h);
    float sa = 1.f / (1.f + expf(-alpha[0]));
    float bb = resb[f];
    float r[4];
    #pragma unroll
    for (int b = 0; b < 4; b++) r[b] = bb;
    #pragma unroll 4
    for (int k = 0; k < 64; k++) {
        float wv = resW[k * 64 + f];
        #pragma unroll
        for (int b = 0; b < 4; b++) r[b] = fmaf(Xsh[nl][b][k], wv, r[b]);
    }
    float4 pr;
    pr.x = r[0] - sa * h; pr.y = r[1] - sa * h;
    pr.z = r[2] - sa * h; pr.w = r[3] - sa * h;
    g_P4[n * 64 + f] = pr;
#if __CUDA_ARCH__ >= 900
    cudaTriggerProgrammaticLaunchCompletion();
#endif
}

// ---------------- K3: sheaf + combine, 8 nodes/block --------------------
// grid 256, block 512. Thread (nl = tid>>6 in 0..7, f) owns all 4 stalk
// rows of node i0+nl (same inner structure as R11). 24-row window covers
// all 8 nodes' neighbors -> 40% less staging traffic than 2x 4-node blocks.
__global__ __launch_bounds__(512)
void k_out(const int* __restrict__ eidx, const float* __restrict__ beta,
           float* __restrict__ out) {
    int tid = threadIdx.x;
    int nl = tid >> 6, f = tid & 63;     // nl in 0..7
    int i0 = blockIdx.x * 8;
    int i = i0 + nl;
    __shared__ float4 Z4sh[24][64];      // rows i0-8 .. i0+15 (mod NE)
    __shared__ float4 offs4[8][64];
    __shared__ int jrel[8][16];

    if (tid < 128) {
        int nn = tid >> 4, kk = tid & 15;
        int pp = (i0 + nn) * 16 + kk;
        int j = eidx[2 * pp + 1];
        jrel[nn][kk] = (j - i0 + 8) & (NE - 1);   // in [0, 24)
    }
#if __CUDA_ARCH__ >= 900
    cudaGridDependencySynchronize();
#endif

    #pragma unroll
    for (int t = 0; t < 3; t++) {
        int idx = tid + t * 512;          // 0..1535
        int row = idx >> 6, ff = idx & 63;
        int src = (i0 - 8 + row) & (NE - 1);
        Z4sh[row][ff] = g_Z4[src * 64 + ff];
    }
    offs4[nl][f] = g_off4[i * 64 + f];
    __syncthreads();

    float4 zi = Z4sh[8 + nl][f];
    const float4* dgr = (const float4*)&g_diag[i * 16];
    float accs[4];
    #pragma unroll
    for (int a = 0; a < 4; a++) {
        float4 d = dgr[a];
        accs[a] = fmaf(d.x, zi.x, fmaf(d.y, zi.y, fmaf(d.z, zi.z, d.w * zi.w)));
    }
    #pragma unroll
    for (int k = 0; k < 16; k++) {
        float4 zj = Z4sh[jrel[nl][k]][f];
        #pragma unroll
        for (int a = 0; a < 4; a++) {
            float4 o = offs4[nl][k * 4 + a];
            accs[a] = fmaf(o.x, zj.x, fmaf(o.y, zj.y, fmaf(o.z, zj.z, fmaf(o.w, zj.w, accs[a]))));
        }
    }
    const float4* dvr = (const float4*)&g_Dinv[i * 16];
    float sh[4];
    #pragma unroll
    for (int a = 0; a < 4; a++) {
        float4 d = dvr[a];
        sh[a] = fmaf(d.x, accs[0], fmaf(d.y, accs[1], fmaf(d.z, accs[2], d.w * accs[3])));
    }

    float4 pr = g_P4[i * 64 + f];
    float sb = 1.f / (1.f + expf(-beta[0]));
    float prr[4] = {pr.x, pr.y, pr.z, pr.w};
    #pragma unroll
    for (int b = 0; b < 4; b++) {
        float e = (sh[b] > 0.f) ? sh[b] : expm1f(sh[b]);
        out[(4 * i + b) * 64 + f] = prr[b] - sb * e;
    }
}

extern "C" void kernel_launch(void* const* d_in, const int* in_sizes, int n_in,
                              void* d_out, int out_size) {
    const float* ef    = (const float*)d_in[0];
    const float* L1    = (const float*)d_in[1];
    const float* X     = (const float*)d_in[2];
    const float* W1    = (const float*)d_in[3];
    const float* b1    = (const float*)d_in[4];
    const float* W2    = (const float*)d_in[5];
    const float* b2    = (const float*)d_in[6];
    const float* W3    = (const float*)d_in[7];
    const float* b3    = (const float*)d_in[8];
    const float* Wh    = (const float*)d_in[9];
    const float* Ws1   = (const float*)d_in[10];
    const float* Ws2   = (const float*)d_in[11];
    const float* resW  = (const float*)d_in[12];
    const float* resb  = (const float*)d_in[13];
    const float* alpha = (const float*)d_in[14];
    const float* beta  = (const float*)d_in[15];
    const int*   eidx  = (const int*)d_in[16];
    const int*   jiidx = (const int*)d_in[17];
    float* out = (float*)d_out;

    k_pre<<<512, 256>>>(ef, W1, b1, X, Ws1, Ws2);

    cudaLaunchAttribute attr[1];
    attr[0].id = cudaLaunchAttributeProgrammaticStreamSerialization;
    attr[0].val.programmaticStreamSerializationAllowed = 1;

    cudaLaunchConfig_t cfg = {};
    cfg.gridDim = dim3(512, 1, 1);
    cfg.blockDim = dim3(256, 1, 1);
    cfg.stream = 0;
    cfg.attrs = attr;
    cfg.numAttrs = 1;

    cudaLaunchKernelEx(&cfg, k_pair, L1, W2, b2, W3, b3, eidx);
    cudaLaunchKernelEx(&cfg, k_mid, eidx, jiidx, Wh, X, resW, resb, alpha);

    cudaLaunchConfig_t cfg_out = {};
    cfg_out.gridDim = dim3(256, 1, 1);
    cfg_out.blockDim = dim3(512, 1, 1);
    cfg_out.stream = 0;
    cfg_out.attrs = attr;
    cfg_out.numAttrs = 1;
    cudaLaunchKernelEx(&cfg_out, k_out, eidx, beta, out);
}